// round 1
// baseline (speedup 1.0000x reference)
#include <cuda_runtime.h>
#include <math.h>

#define NTOK 8192
#define DDIM 1024
#define NSEM 8192
#define NLRN 128
#define NCB  8320   // NSEM + NLRN

// Scratch (allocation-free rule: __device__ globals)
__device__ float g_xn[(size_t)NTOK * DDIM];
__device__ float g_cb[(size_t)NCB * DDIM];
__device__ float g_rowloss[NTOK];
__device__ int   g_idx[NTOK];

// ---------------------------------------------------------------------------
// Row L2-normalize: one block per row, 256 threads, one float4 per thread.
// ---------------------------------------------------------------------------
__global__ void norm_rows(const float* __restrict__ src, float* __restrict__ dst) {
    int r = blockIdx.x;
    const float4* s = (const float4*)(src + (size_t)r * DDIM);
    float4 v = s[threadIdx.x];
    float ss = v.x * v.x + v.y * v.y + v.z * v.z + v.w * v.w;
    #pragma unroll
    for (int o = 16; o; o >>= 1) ss += __shfl_xor_sync(0xffffffffu, ss, o);
    __shared__ float red[8];
    __shared__ float inv_s;
    if ((threadIdx.x & 31) == 0) red[threadIdx.x >> 5] = ss;
    __syncthreads();
    if (threadIdx.x == 0) {
        float t = 0.f;
        #pragma unroll
        for (int i = 0; i < 8; i++) t += red[i];
        inv_s = 1.0f / fmaxf(sqrtf(t), 1e-8f);
    }
    __syncthreads();
    float inv = inv_s;
    float4 o4 = make_float4(v.x * inv, v.y * inv, v.z * inv, v.w * inv);
    ((float4*)(dst + (size_t)r * DDIM))[threadIdx.x] = o4;
}

// ---------------------------------------------------------------------------
// fp32 NT GEMM: logits[N, C] = xn[N, D] * cb[C, D]^T
// 128x128 tile, BK=16, 256 threads, 8x8 per-thread micro-tile.
// N=8192=64*128, C=8320=65*128, D=1024=64*16 -> no bounds checks.
// ---------------------------------------------------------------------------
__global__ void __launch_bounds__(256, 2)
gemm_nt(const float* __restrict__ A, const float* __restrict__ B,
        float* __restrict__ Cout) {
    __shared__ float As[16][128];
    __shared__ float Bs[16][128];
    int tid = threadIdx.x;
    int bx = blockIdx.x;            // codebook tile (65)
    int by = blockIdx.y;            // token tile (64)
    int tx = tid & 15, ty = tid >> 4;
    const float* Ab = A + (size_t)by * 128 * DDIM;
    const float* Bb = B + (size_t)bx * 128 * DDIM;

    float acc[8][8];
    #pragma unroll
    for (int i = 0; i < 8; i++)
        #pragma unroll
        for (int j = 0; j < 8; j++) acc[i][j] = 0.f;

    int lrow = tid >> 2;            // 0..63
    int lcg  = (tid & 3) * 4;       // 0,4,8,12

    for (int kt = 0; kt < DDIM; kt += 16) {
        #pragma unroll
        for (int h = 0; h < 2; h++) {
            int r = lrow + h * 64;
            float4 av = *(const float4*)(Ab + (size_t)r * DDIM + kt + lcg);
            As[lcg + 0][r] = av.x; As[lcg + 1][r] = av.y;
            As[lcg + 2][r] = av.z; As[lcg + 3][r] = av.w;
            float4 bv = *(const float4*)(Bb + (size_t)r * DDIM + kt + lcg);
            Bs[lcg + 0][r] = bv.x; Bs[lcg + 1][r] = bv.y;
            Bs[lcg + 2][r] = bv.z; Bs[lcg + 3][r] = bv.w;
        }
        __syncthreads();
        #pragma unroll
        for (int kk = 0; kk < 16; kk++) {
            float a[8], b[8];
            *(float4*)(a)     = *(float4*)&As[kk][ty * 8];
            *(float4*)(a + 4) = *(float4*)&As[kk][ty * 8 + 4];
            *(float4*)(b)     = *(float4*)&Bs[kk][tx * 8];
            *(float4*)(b + 4) = *(float4*)&Bs[kk][tx * 8 + 4];
            #pragma unroll
            for (int i = 0; i < 8; i++)
                #pragma unroll
                for (int j = 0; j < 8; j++)
                    acc[i][j] = fmaf(a[i], b[j], acc[i][j]);
        }
        __syncthreads();
    }

    int row0 = by * 128 + ty * 8;
    int col0 = bx * 128 + tx * 8;
    #pragma unroll
    for (int i = 0; i < 8; i++) {
        float4* p = (float4*)(Cout + (size_t)(row0 + i) * NCB + col0);
        p[0] = *(float4*)&acc[i][0];
        p[1] = *(float4*)&acc[i][4];
    }
}

// ---------------------------------------------------------------------------
// Per-row argmax over 8320 logits + gather z_q + exact z_q_st epilogue.
// Tie-break: lowest index (matches jnp.argmax first-occurrence).
// ---------------------------------------------------------------------------
__global__ void argmax_gather(const float* __restrict__ logits,
                              float* __restrict__ idx_out,
                              float* __restrict__ zq,
                              float* __restrict__ zqst) {
    int r = blockIdx.x;
    const float* row = logits + (size_t)r * NCB;
    float best = -1e30f; int bi = 0;
    for (int c = threadIdx.x; c < NCB; c += 256) {
        float v = row[c];
        if (v > best) { best = v; bi = c; }
    }
    __shared__ float sv[256];
    __shared__ int   si[256];
    sv[threadIdx.x] = best; si[threadIdx.x] = bi;
    __syncthreads();
    #pragma unroll
    for (int off = 128; off; off >>= 1) {
        if (threadIdx.x < off) {
            float v2 = sv[threadIdx.x + off]; int i2 = si[threadIdx.x + off];
            float v1 = sv[threadIdx.x];       int i1 = si[threadIdx.x];
            if (v2 > v1 || (v2 == v1 && i2 < i1)) { sv[threadIdx.x] = v2; si[threadIdx.x] = i2; }
        }
        __syncthreads();
    }
    int idx = si[0];
    if (threadIdx.x == 0) {
        idx_out[r]   = (float)idx;
        g_idx[r]     = idx;
        g_rowloss[r] = 1.0f - sv[0];
    }
    const float4 cv = ((const float4*)(g_cb + (size_t)idx * DDIM))[threadIdx.x];
    const float4 xv = ((const float4*)(g_xn + (size_t)r   * DDIM))[threadIdx.x];
    ((float4*)(zq + (size_t)r * DDIM))[threadIdx.x] = cv;
    // z_q_st = xn + (z_q - xn): keep the exact fp op order of the reference
    float4 st = make_float4(xv.x + (cv.x - xv.x), xv.y + (cv.y - xv.y),
                            xv.z + (cv.z - xv.z), xv.w + (cv.w - xv.w));
    ((float4*)(zqst + (size_t)r * DDIM))[threadIdx.x] = st;
}

// ---------------------------------------------------------------------------
// Deterministic loss reduction (single block, fixed tree — no float atomics).
// cos_sim(xn, z_q) == maxlogit since both rows are unit-normalized.
// ---------------------------------------------------------------------------
__global__ void reduce_losses(float* __restrict__ scal) {
    __shared__ float scom[1024];
    __shared__ float svq[1024];
    __shared__ int   scnt[1024];
    float cm = 0.f, vq = 0.f; int cnt = 0;
    for (int r = threadIdx.x; r < NTOK; r += 1024) {
        float l = g_rowloss[r];
        cm += l;
        if (g_idx[r] >= NSEM) { vq += l; cnt++; }
    }
    scom[threadIdx.x] = cm; svq[threadIdx.x] = vq; scnt[threadIdx.x] = cnt;
    __syncthreads();
    #pragma unroll
    for (int off = 512; off; off >>= 1) {
        if (threadIdx.x < off) {
            scom[threadIdx.x] += scom[threadIdx.x + off];
            svq[threadIdx.x]  += svq[threadIdx.x + off];
            scnt[threadIdx.x] += scnt[threadIdx.x + off];
        }
        __syncthreads();
    }
    if (threadIdx.x == 0) {
        float commitment = scom[0] / (float)NTOK;
        float vql = svq[0] / ((float)scnt[0] + 1e-6f);
        scal[0] = vql;                      // vq_loss
        scal[1] = commitment;               // commitment_loss
        scal[2] = vql + 0.25f * commitment; // quant_loss
    }
}

// ---------------------------------------------------------------------------
extern "C" void kernel_launch(void* const* d_in, const int* in_sizes, int n_in,
                              void* d_out, int out_size) {
    const float* x   = (const float*)d_in[0];
    const float* sem = (const float*)d_in[1];
    const float* lrn = (const float*)d_in[2];
    float* out = (float*)d_out;

    float* logits = out;
    float* idxf   = out  + (size_t)NTOK * NCB;
    float* zq     = idxf + NTOK;
    float* zqst   = zq   + (size_t)NTOK * DDIM;
    float* scal   = zqst + (size_t)NTOK * DDIM;

    float *p_xn, *p_cb;
    cudaGetSymbolAddress((void**)&p_xn, g_xn);
    cudaGetSymbolAddress((void**)&p_cb, g_cb);

    norm_rows<<<NTOK, 256>>>(x,   p_xn);
    norm_rows<<<NSEM, 256>>>(sem, p_cb);
    norm_rows<<<NLRN, 256>>>(lrn, p_cb + (size_t)NSEM * DDIM);

    dim3 grid(NCB / 128, NTOK / 128);
    gemm_nt<<<grid, 256>>>(p_xn, p_cb, logits);

    argmax_gather<<<NTOK, 256>>>(logits, idxf, zq, zqst);
    reduce_losses<<<1, 1024>>>(scal);
}

// round 3
// speedup vs baseline: 2.9255x; 2.9255x over previous
#include <cuda_runtime.h>
#include <cuda_fp16.h>
#include <math.h>
#include <stdint.h>

#define NTOK 8192
#define DDIM 1024
#define NSEM 8192
#define NLRN 128
#define NCB  8320           // NSEM + NLRN
#define KEXT 3072           // 3 * DDIM (split products: a0b0, a0b1, a1b0)
#define NCBP 8448           // NCB padded to 33*256

#define TILE_M 128
#define TILE_N 256
#define BK     64           // fp16 elems per K-chunk (128B row)
#define NKCH   (KEXT / BK)  // 48
#define STAGES 3
#define A_BYTES (TILE_M * 128)            // 16KB
#define B_BYTES (TILE_N * 128)            // 32KB
#define STAGE_BYTES (A_BYTES + B_BYTES)   // 48KB

// ---------------- scratch (__device__ globals; no allocs) -------------------
__device__ __align__(128) float  g_xn[(size_t)NTOK * DDIM];
__device__ __align__(128) float  g_cb[(size_t)NCB * DDIM];
__device__ __align__(128) __half g_Aext[(size_t)NTOK * KEXT];
__device__ __align__(128) __half g_Bext[(size_t)NCBP * KEXT];
__device__ float g_rowloss[NTOK];
__device__ int   g_idx[NTOK];

// ---------------- PTX helpers ----------------------------------------------
__device__ __forceinline__ uint32_t smem_u32(const void* p) {
    uint32_t a;
    asm("{ .reg .u64 t; cvta.to.shared.u64 t, %1; cvt.u32.u64 %0, t; }" : "=r"(a) : "l"(p));
    return a;
}
__device__ __forceinline__ uint32_t sw128(uint32_t x) { return x ^ ((x >> 3) & 0x70); }

__device__ __forceinline__ void cp_async16(uint32_t dst, const void* src) {
    asm volatile("cp.async.cg.shared.global [%0], [%1], 16;" :: "r"(dst), "l"(src) : "memory");
}
#define CP_COMMIT() asm volatile("cp.async.commit_group;" ::: "memory")
#define CP_WAIT(n)  asm volatile("cp.async.wait_group %0;" :: "n"(n) : "memory")

#define LDSM_X4(r0, r1, r2, r3, a) \
    asm volatile("ldmatrix.sync.aligned.m8n8.x4.shared.b16 {%0,%1,%2,%3}, [%4];" \
                 : "=r"(r0), "=r"(r1), "=r"(r2), "=r"(r3) : "r"(a))

#define MMA16816(c, a, b0, b1) \
    asm volatile("mma.sync.aligned.m16n8k16.row.col.f32.f16.f16.f32 " \
                 "{%0,%1,%2,%3},{%4,%5,%6,%7},{%8,%9},{%0,%1,%2,%3};" \
                 : "+f"((c)[0]), "+f"((c)[1]), "+f"((c)[2]), "+f"((c)[3]) \
                 : "r"((a)[0]), "r"((a)[1]), "r"((a)[2]), "r"((a)[3]), "r"(b0), "r"(b1))

// ---------------------------------------------------------------------------
// normalize + fp16 2-way split.
// A layout: a0 -> segs {0,1}, a1 -> seg {2}
// B layout: b0 -> segs {0,2}, b1 -> seg {1}
// => one K=3072 GEMM accumulates a0b0 + a0b1 + a1b0 exactly.
// ---------------------------------------------------------------------------
template <int ALAYOUT>
__global__ void norm_split(const float* __restrict__ src, float* __restrict__ f32dst,
                           __half* __restrict__ ext, int row0) {
    int r = blockIdx.x;
    int t = threadIdx.x;
    float4 v = ((const float4*)(src + (size_t)r * DDIM))[t];
    float ss = v.x * v.x + v.y * v.y + v.z * v.z + v.w * v.w;
    #pragma unroll
    for (int o = 16; o; o >>= 1) ss += __shfl_xor_sync(0xffffffffu, ss, o);
    __shared__ float red[8];
    __shared__ float inv_s;
    if ((t & 31) == 0) red[t >> 5] = ss;
    __syncthreads();
    if (t == 0) {
        float s = 0.f;
        #pragma unroll
        for (int i = 0; i < 8; i++) s += red[i];
        inv_s = 1.0f / fmaxf(sqrtf(s), 1e-8f);
    }
    __syncthreads();
    float inv = inv_s;
    float f[4] = { v.x * inv, v.y * inv, v.z * inv, v.w * inv };
    ((float4*)(f32dst + (size_t)r * DDIM))[t] = *(float4*)f;

    union { __half h[4]; uint2 u; } p0, p1;
    #pragma unroll
    for (int j = 0; j < 4; j++) {
        __half h0 = __float2half_rn(f[j]);
        float r1 = f[j] - __half2float(h0);
        p0.h[j] = h0;
        p1.h[j] = __float2half_rn(r1);
    }
    __half* base = ext + (size_t)(row0 + r) * KEXT + 4 * t;
    if (ALAYOUT) {
        *(uint2*)(base + 0 * DDIM) = p0.u;
        *(uint2*)(base + 1 * DDIM) = p0.u;
        *(uint2*)(base + 2 * DDIM) = p1.u;
    } else {
        *(uint2*)(base + 0 * DDIM) = p0.u;
        *(uint2*)(base + 2 * DDIM) = p0.u;
        *(uint2*)(base + 1 * DDIM) = p1.u;
    }
}

__global__ void pad_bext() {   // zero rows [NCB, NCBP)
    int r = NCB + blockIdx.x;
    uint4 z = make_uint4(0, 0, 0, 0);
    uint4* p = (uint4*)(g_Bext + (size_t)r * KEXT);
    for (int i = threadIdx.x; i < KEXT * 2 / 16; i += blockDim.x) p[i] = z;
}

// ---------------------------------------------------------------------------
// fp16 mma.sync GEMM: logits[8192, 8320] = Aext[8192,3072] @ Bext[8448,3072]^T
// CTA 128x256, 8 warps (2x4), warp tile 64x64, BK=64, 3-stage cp.async.
// ---------------------------------------------------------------------------
__device__ __forceinline__ void load_chunk(const __half* __restrict__ Aext,
                                           const __half* __restrict__ Bext,
                                           uint32_t data_base, int stage,
                                           int by, int bx, int kc, int tid) {
    uint32_t sb = data_base + stage * STAGE_BYTES;
    const char* Ab = (const char*)Aext + (size_t)by * TILE_M * (KEXT * 2) + (size_t)kc * 128;
    const char* Bb = (const char*)Bext + (size_t)bx * TILE_N * (KEXT * 2) + (size_t)kc * 128;
    // A: 128 rows * 8 cp16 = 1024 ops -> 4 per thread
    #pragma unroll
    for (int i = 0; i < 4; i++) {
        int c = tid + i * 256;
        int row = c >> 3, cg = c & 7;
        cp_async16(sb + sw128(row * 128 + cg * 16),
                   Ab + (size_t)row * (KEXT * 2) + cg * 16);
    }
    // B: 256 rows * 8 = 2048 ops -> 8 per thread
    #pragma unroll
    for (int i = 0; i < 8; i++) {
        int c = tid + i * 256;
        int row = c >> 3, cg = c & 7;
        cp_async16(sb + A_BYTES + sw128(row * 128 + cg * 16),
                   Bb + (size_t)row * (KEXT * 2) + cg * 16);
    }
    CP_COMMIT();
}

__global__ void __launch_bounds__(256, 1)
gemm_mma(const __half* __restrict__ Aext, const __half* __restrict__ Bext,
         float* __restrict__ Cout) {
    extern __shared__ char smem[];
    uint32_t data_base = smem_u32(smem);

    int tid = threadIdx.x, wid = tid >> 5, lane = tid & 31;
    int bx = blockIdx.x, by = blockIdx.y;
    int warp_m = wid & 1;       // 2 warps over M
    int warp_n = wid >> 1;      // 4 warps over N

    // ldmatrix per-lane address components
    int rowA = lane & 15;                 // row within 16-row tile
    int kselA = (lane >> 4) * 16;         // 0 or 16 bytes (k half)
    int rowB = (lane & 7) + ((lane >> 4) & 1) * 8;
    int kselB = ((lane >> 3) & 1) * 16;

    float acc[4][8][4];
    #pragma unroll
    for (int i = 0; i < 4; i++)
        #pragma unroll
        for (int j = 0; j < 8; j++)
            #pragma unroll
            for (int q = 0; q < 4; q++) acc[i][j][q] = 0.f;

    load_chunk(Aext, Bext, data_base, 0, by, bx, 0, tid);
    load_chunk(Aext, Bext, data_base, 1, by, bx, 1, tid);

    for (int k = 0; k < NKCH; k++) {
        int s = k - (k / STAGES) * STAGES;
        if (k + 2 < NKCH) CP_WAIT(1); else CP_WAIT(0);
        __syncthreads();
        if (k + 2 < NKCH) {
            int ss = (k + 2) - ((k + 2) / STAGES) * STAGES;
            load_chunk(Aext, Bext, data_base, ss, by, bx, k + 2, tid);
        }
        uint32_t Ab = data_base + s * STAGE_BYTES;
        uint32_t Bb = Ab + A_BYTES;
        #pragma unroll
        for (int ks = 0; ks < 4; ks++) {
            uint32_t afr[4][4];
            #pragma unroll
            for (int mt = 0; mt < 4; mt++) {
                uint32_t off = (uint32_t)(warp_m * 64 + mt * 16 + rowA) * 128
                             + ks * 32 + kselA;
                LDSM_X4(afr[mt][0], afr[mt][1], afr[mt][2], afr[mt][3], Ab + sw128(off));
            }
            uint32_t bfr[4][4];
            #pragma unroll
            for (int np = 0; np < 4; np++) {
                uint32_t off = (uint32_t)(warp_n * 64 + np * 16 + rowB) * 128
                             + ks * 32 + kselB;
                LDSM_X4(bfr[np][0], bfr[np][1], bfr[np][2], bfr[np][3], Bb + sw128(off));
            }
            #pragma unroll
            for (int mt = 0; mt < 4; mt++)
                #pragma unroll
                for (int nt = 0; nt < 8; nt++)
                    MMA16816(acc[mt][nt], afr[mt],
                             bfr[nt >> 1][(nt & 1) * 2], bfr[nt >> 1][(nt & 1) * 2 + 1]);
        }
        __syncthreads();
    }

    // epilogue: direct fp32 stores (guard N tail: cols >= NCB are padding)
    int row_base = by * TILE_M + warp_m * 64;
    int col_base = bx * TILE_N + warp_n * 64;
    #pragma unroll
    for (int mt = 0; mt < 4; mt++) {
        int r0 = row_base + mt * 16 + (lane >> 2);
        #pragma unroll
        for (int nt = 0; nt < 8; nt++) {
            int c0 = col_base + nt * 8 + (lane & 3) * 2;
            if (c0 < NCB) {
                float2* p0 = (float2*)(Cout + (size_t)r0 * NCB + c0);
                float2* p1 = (float2*)(Cout + (size_t)(r0 + 8) * NCB + c0);
                *p0 = make_float2(acc[mt][nt][0], acc[mt][nt][1]);
                *p1 = make_float2(acc[mt][nt][2], acc[mt][nt][3]);
            }
        }
    }
}

// ---------------------------------------------------------------------------
// argmax + gather + z_q_st (exact reference fp order), per row
// ---------------------------------------------------------------------------
__global__ void argmax_gather(const float* __restrict__ logits,
                              float* __restrict__ idx_out,
                              float* __restrict__ zq,
                              float* __restrict__ zqst) {
    int r = blockIdx.x;
    const float* row = logits + (size_t)r * NCB;
    float best = -1e30f; int bi = 0;
    for (int c = threadIdx.x; c < NCB; c += 256) {
        float v = row[c];
        if (v > best) { best = v; bi = c; }
    }
    __shared__ float sv[256];
    __shared__ int   si[256];
    sv[threadIdx.x] = best; si[threadIdx.x] = bi;
    __syncthreads();
    #pragma unroll
    for (int off = 128; off; off >>= 1) {
        if (threadIdx.x < off) {
            float v2 = sv[threadIdx.x + off]; int i2 = si[threadIdx.x + off];
            float v1 = sv[threadIdx.x];       int i1 = si[threadIdx.x];
            if (v2 > v1 || (v2 == v1 && i2 < i1)) { sv[threadIdx.x] = v2; si[threadIdx.x] = i2; }
        }
        __syncthreads();
    }
    int idx = si[0];
    if (threadIdx.x == 0) {
        idx_out[r]   = (float)idx;
        g_idx[r]     = idx;
        g_rowloss[r] = 1.0f - sv[0];
    }
    const float4 cv = ((const float4*)(g_cb + (size_t)idx * DDIM))[threadIdx.x];
    const float4 xv = ((const float4*)(g_xn + (size_t)r   * DDIM))[threadIdx.x];
    ((float4*)(zq + (size_t)r * DDIM))[threadIdx.x] = cv;
    float4 st = make_float4(xv.x + (cv.x - xv.x), xv.y + (cv.y - xv.y),
                            xv.z + (cv.z - xv.z), xv.w + (cv.w - xv.w));
    ((float4*)(zqst + (size_t)r * DDIM))[threadIdx.x] = st;
}

__global__ void reduce_losses(float* __restrict__ scal) {
    __shared__ float scom[1024];
    __shared__ float svq[1024];
    __shared__ int   scnt[1024];
    float cm = 0.f, vq = 0.f; int cnt = 0;
    for (int r = threadIdx.x; r < NTOK; r += 1024) {
        float l = g_rowloss[r];
        cm += l;
        if (g_idx[r] >= NSEM) { vq += l; cnt++; }
    }
    scom[threadIdx.x] = cm; svq[threadIdx.x] = vq; scnt[threadIdx.x] = cnt;
    __syncthreads();
    #pragma unroll
    for (int off = 512; off; off >>= 1) {
        if (threadIdx.x < off) {
            scom[threadIdx.x] += scom[threadIdx.x + off];
            svq[threadIdx.x]  += svq[threadIdx.x + off];
            scnt[threadIdx.x] += scnt[threadIdx.x + off];
        }
        __syncthreads();
    }
    if (threadIdx.x == 0) {
        float commitment = scom[0] / (float)NTOK;
        float vql = svq[0] / ((float)scnt[0] + 1e-6f);
        scal[0] = vql;
        scal[1] = commitment;
        scal[2] = vql + 0.25f * commitment;
    }
}

// ---------------------------------------------------------------------------
extern "C" void kernel_launch(void* const* d_in, const int* in_sizes, int n_in,
                              void* d_out, int out_size) {
    const float* x   = (const float*)d_in[0];
    const float* sem = (const float*)d_in[1];
    const float* lrn = (const float*)d_in[2];
    float* out = (float*)d_out;

    float* logits = out;
    float* idxf   = out  + (size_t)NTOK * NCB;
    float* zq     = idxf + NTOK;
    float* zqst   = zq   + (size_t)NTOK * DDIM;
    float* scal   = zqst + (size_t)NTOK * DDIM;

    float *p_xn, *p_cb;
    __half *p_A, *p_B;
    cudaGetSymbolAddress((void**)&p_xn, g_xn);
    cudaGetSymbolAddress((void**)&p_cb, g_cb);
    cudaGetSymbolAddress((void**)&p_A,  g_Aext);
    cudaGetSymbolAddress((void**)&p_B,  g_Bext);

    norm_split<1><<<NTOK, 256>>>(x,   p_xn, p_A, 0);
    norm_split<0><<<NSEM, 256>>>(sem, p_cb, p_B, 0);
    norm_split<0><<<NLRN, 256>>>(lrn, p_cb + (size_t)NSEM * DDIM, p_B, NSEM);
    pad_bext<<<NCBP - NCB, 256>>>();

    int smem_bytes = STAGES * STAGE_BYTES;   // 144KB
    cudaFuncSetAttribute(gemm_mma, cudaFuncAttributeMaxDynamicSharedMemorySize, smem_bytes);
    dim3 grid(NCBP / TILE_N, NTOK / TILE_M);   // 33 x 64
    gemm_mma<<<grid, 256, smem_bytes>>>(p_A, p_B, logits);

    argmax_gather<<<NTOK, 256>>>(logits, idxf, zq, zqst);
    reduce_losses<<<1, 1024>>>(scal);
}

// round 4
// speedup vs baseline: 3.0372x; 1.0382x over previous
#include <cuda_runtime.h>
#include <cuda_fp16.h>
#include <math.h>
#include <stdint.h>

#define NTOK 8192
#define DDIM 1024
#define NSEM 8192
#define NLRN 128
#define NCB  8320           // NSEM + NLRN
#define KEXT 3072           // 3 * DDIM (split products: a0b0, a0b1, a1b0)
#define NCBP 8448           // NCB padded to 33*256
#define NXT  33             // column tiles

#define TILE_M 128
#define TILE_N 256
#define BK     64           // fp16 elems per K-chunk (128B row)
#define NKCH   (KEXT / BK)  // 48
#define STAGES 4
#define A_BYTES (TILE_M * 128)            // 16KB
#define B_BYTES (TILE_N * 128)            // 32KB
#define STAGE_BYTES (A_BYTES + B_BYTES)   // 48KB

// ---------------- scratch (__device__ globals; no allocs) -------------------
__device__ __align__(128) float  g_xn[(size_t)NTOK * DDIM];
__device__ __align__(128) float  g_cb[(size_t)NCB * DDIM];
__device__ __align__(128) __half g_Aext[(size_t)NTOK * KEXT];
__device__ __align__(128) __half g_Bext[(size_t)NCBP * KEXT];
__device__ float g_pval[(size_t)NTOK * NXT];
__device__ int   g_pcol[(size_t)NTOK * NXT];
__device__ float g_rowloss[NTOK];
__device__ int   g_idx[NTOK];

// ---------------- PTX helpers ----------------------------------------------
__device__ __forceinline__ uint32_t smem_u32(const void* p) {
    uint32_t a;
    asm("{ .reg .u64 t; cvta.to.shared.u64 t, %1; cvt.u32.u64 %0, t; }" : "=r"(a) : "l"(p));
    return a;
}
__device__ __forceinline__ uint32_t sw128(uint32_t x) { return x ^ ((x >> 3) & 0x70); }

__device__ __forceinline__ void cp_async16(uint32_t dst, const void* src) {
    asm volatile("cp.async.cg.shared.global [%0], [%1], 16;" :: "r"(dst), "l"(src) : "memory");
}
#define CP_COMMIT() asm volatile("cp.async.commit_group;" ::: "memory")
#define CP_WAIT(n)  asm volatile("cp.async.wait_group %0;" :: "n"(n) : "memory")

#define LDSM_X4(r0, r1, r2, r3, a) \
    asm volatile("ldmatrix.sync.aligned.m8n8.x4.shared.b16 {%0,%1,%2,%3}, [%4];" \
                 : "=r"(r0), "=r"(r1), "=r"(r2), "=r"(r3) : "r"(a))

#define MMA16816(c, a, b0, b1) \
    asm volatile("mma.sync.aligned.m16n8k16.row.col.f32.f16.f16.f32 " \
                 "{%0,%1,%2,%3},{%4,%5,%6,%7},{%8,%9},{%0,%1,%2,%3};" \
                 : "+f"((c)[0]), "+f"((c)[1]), "+f"((c)[2]), "+f"((c)[3]) \
                 : "r"((a)[0]), "r"((a)[1]), "r"((a)[2]), "r"((a)[3]), "r"(b0), "r"(b1))

// ---------------------------------------------------------------------------
// normalize + fp16 2-way split.
// A layout: a0 -> segs {0,1}, a1 -> seg {2}
// B layout: b0 -> segs {0,2}, b1 -> seg {1}
// => one K=3072 GEMM accumulates a0b0 + a0b1 + a1b0.
// ---------------------------------------------------------------------------
template <int ALAYOUT>
__global__ void norm_split(const float* __restrict__ src, float* __restrict__ f32dst,
                           __half* __restrict__ ext, int row0) {
    int r = blockIdx.x;
    int t = threadIdx.x;
    float4 v = ((const float4*)(src + (size_t)r * DDIM))[t];
    float ss = v.x * v.x + v.y * v.y + v.z * v.z + v.w * v.w;
    #pragma unroll
    for (int o = 16; o; o >>= 1) ss += __shfl_xor_sync(0xffffffffu, ss, o);
    __shared__ float red[8];
    __shared__ float inv_s;
    if ((t & 31) == 0) red[t >> 5] = ss;
    __syncthreads();
    if (t == 0) {
        float s = 0.f;
        #pragma unroll
        for (int i = 0; i < 8; i++) s += red[i];
        inv_s = 1.0f / fmaxf(sqrtf(s), 1e-8f);
    }
    __syncthreads();
    float inv = inv_s;
    float f[4] = { v.x * inv, v.y * inv, v.z * inv, v.w * inv };
    ((float4*)(f32dst + (size_t)r * DDIM))[t] = *(float4*)f;

    union { __half h[4]; uint2 u; } p0, p1;
    #pragma unroll
    for (int j = 0; j < 4; j++) {
        __half h0 = __float2half_rn(f[j]);
        float r1 = f[j] - __half2float(h0);
        p0.h[j] = h0;
        p1.h[j] = __float2half_rn(r1);
    }
    __half* base = ext + (size_t)(row0 + r) * KEXT + 4 * t;
    if (ALAYOUT) {
        *(uint2*)(base + 0 * DDIM) = p0.u;
        *(uint2*)(base + 1 * DDIM) = p0.u;
        *(uint2*)(base + 2 * DDIM) = p1.u;
    } else {
        *(uint2*)(base + 0 * DDIM) = p0.u;
        *(uint2*)(base + 2 * DDIM) = p0.u;
        *(uint2*)(base + 1 * DDIM) = p1.u;
    }
}

__global__ void pad_bext() {   // zero rows [NCB, NCBP)
    int r = NCB + blockIdx.x;
    uint4 z = make_uint4(0, 0, 0, 0);
    uint4* p = (uint4*)(g_Bext + (size_t)r * KEXT);
    for (int i = threadIdx.x; i < KEXT * 2 / 16; i += blockDim.x) p[i] = z;
}

// ---------------------------------------------------------------------------
// fp16 mma.sync GEMM + fused per-tile row argmax.
// CTA 128x256, 8 warps (2x4), warp tile 64x64, BK=64, 4-stage cp.async,
// one __syncthreads per chunk.
// ---------------------------------------------------------------------------
__device__ __forceinline__ void load_chunk(const __half* __restrict__ Aext,
                                           const __half* __restrict__ Bext,
                                           uint32_t data_base, int stage,
                                           int by, int bx, int kc, int tid) {
    uint32_t sb = data_base + stage * STAGE_BYTES;
    const char* Ab = (const char*)Aext + (size_t)by * TILE_M * (KEXT * 2) + (size_t)kc * 128;
    const char* Bb = (const char*)Bext + (size_t)bx * TILE_N * (KEXT * 2) + (size_t)kc * 128;
    #pragma unroll
    for (int i = 0; i < 4; i++) {
        int c = tid + i * 256;
        int row = c >> 3, cg = c & 7;
        cp_async16(sb + sw128(row * 128 + cg * 16),
                   Ab + (size_t)row * (KEXT * 2) + cg * 16);
    }
    #pragma unroll
    for (int i = 0; i < 8; i++) {
        int c = tid + i * 256;
        int row = c >> 3, cg = c & 7;
        cp_async16(sb + A_BYTES + sw128(row * 128 + cg * 16),
                   Bb + (size_t)row * (KEXT * 2) + cg * 16);
    }
    CP_COMMIT();
}

__global__ void __launch_bounds__(256, 1)
gemm_mma(const __half* __restrict__ Aext, const __half* __restrict__ Bext,
         float* __restrict__ Cout) {
    extern __shared__ char smem[];
    uint32_t data_base = smem_u32(smem);

    int tid = threadIdx.x, wid = tid >> 5, lane = tid & 31;
    int bx = blockIdx.x, by = blockIdx.y;
    int warp_m = wid & 1;       // 2 warps over M
    int warp_n = wid >> 1;      // 4 warps over N

    int rowA = lane & 15;
    int kselA = (lane >> 4) * 16;
    int rowB = (lane & 7) + ((lane >> 4) & 1) * 8;
    int kselB = ((lane >> 3) & 1) * 16;

    float acc[4][8][4];
    #pragma unroll
    for (int i = 0; i < 4; i++)
        #pragma unroll
        for (int j = 0; j < 8; j++)
            #pragma unroll
            for (int q = 0; q < 4; q++) acc[i][j][q] = 0.f;

    load_chunk(Aext, Bext, data_base, 0, by, bx, 0, tid);
    load_chunk(Aext, Bext, data_base, 1, by, bx, 1, tid);
    load_chunk(Aext, Bext, data_base, 2, by, bx, 2, tid);

    for (int k = 0; k < NKCH; k++) {
        if (k < NKCH - 2)      CP_WAIT(2);
        else if (k == NKCH - 2) CP_WAIT(1);
        else                    CP_WAIT(0);
        __syncthreads();
        if (k + 3 < NKCH) {
            int ss = (k + 3) & (STAGES - 1);
            load_chunk(Aext, Bext, data_base, ss, by, bx, k + 3, tid);
        }
        int s = k & (STAGES - 1);
        uint32_t Ab = data_base + s * STAGE_BYTES;
        uint32_t Bb = Ab + A_BYTES;
        #pragma unroll
        for (int ks = 0; ks < 4; ks++) {
            uint32_t afr[4][4];
            #pragma unroll
            for (int mt = 0; mt < 4; mt++) {
                uint32_t off = (uint32_t)(warp_m * 64 + mt * 16 + rowA) * 128
                             + ks * 32 + kselA;
                LDSM_X4(afr[mt][0], afr[mt][1], afr[mt][2], afr[mt][3], Ab + sw128(off));
            }
            uint32_t bfr[4][4];
            #pragma unroll
            for (int np = 0; np < 4; np++) {
                uint32_t off = (uint32_t)(warp_n * 64 + np * 16 + rowB) * 128
                             + ks * 32 + kselB;
                LDSM_X4(bfr[np][0], bfr[np][1], bfr[np][2], bfr[np][3], Bb + sw128(off));
            }
            #pragma unroll
            for (int mt = 0; mt < 4; mt++)
                #pragma unroll
                for (int nt = 0; nt < 8; nt++)
                    MMA16816(acc[mt][nt], afr[mt],
                             bfr[nt >> 1][(nt & 1) * 2], bfr[nt >> 1][(nt & 1) * 2 + 1]);
        }
    }
    __syncthreads();   // all compute done; smem free for reuse

    // ---- store logits ----
    int row_base = by * TILE_M + warp_m * 64;
    int col_base = bx * TILE_N + warp_n * 64;
    #pragma unroll
    for (int mt = 0; mt < 4; mt++) {
        int r0 = row_base + mt * 16 + (lane >> 2);
        #pragma unroll
        for (int nt = 0; nt < 8; nt++) {
            int c0 = col_base + nt * 8 + (lane & 3) * 2;
            if (c0 < NCB) {
                float2* p0 = (float2*)(Cout + (size_t)r0 * NCB + c0);
                float2* p1 = (float2*)(Cout + (size_t)(r0 + 8) * NCB + c0);
                *p0 = make_float2(acc[mt][nt][0], acc[mt][nt][1]);
                *p1 = make_float2(acc[mt][nt][2], acc[mt][nt][3]);
            }
        }
    }

    // ---- fused per-tile row argmax ----
    float* bufv = (float*)smem;            // [128][4]
    int*   bufi = (int*)(smem + 2048);     // [128][4]
    #pragma unroll
    for (int mt = 0; mt < 4; mt++) {
        #pragma unroll
        for (int h = 0; h < 2; h++) {
            float bv = -1e30f; int bc = 0x7fffffff;
            #pragma unroll
            for (int nt = 0; nt < 8; nt++) {
                #pragma unroll
                for (int qq = 0; qq < 2; qq++) {
                    int colg = col_base + nt * 8 + (lane & 3) * 2 + qq;
                    float v = (colg < NCB) ? acc[mt][nt][h * 2 + qq] : -1e30f;
                    if (v > bv) { bv = v; bc = colg; }
                }
            }
            #pragma unroll
            for (int off = 1; off <= 2; off <<= 1) {
                float ov = __shfl_xor_sync(0xffffffffu, bv, off);
                int   oc = __shfl_xor_sync(0xffffffffu, bc, off);
                if (ov > bv || (ov == bv && oc < bc)) { bv = ov; bc = oc; }
            }
            if ((lane & 3) == 0) {
                int rl = warp_m * 64 + mt * 16 + (lane >> 2) + h * 8;
                bufv[rl * 4 + warp_n] = bv;
                bufi[rl * 4 + warp_n] = bc;
            }
        }
    }
    __syncthreads();
    if (tid < 128) {
        float bv = -1e30f; int bc = 0x7fffffff;
        #pragma unroll
        for (int w = 0; w < 4; w++) {
            float v = bufv[tid * 4 + w]; int c = bufi[tid * 4 + w];
            if (v > bv || (v == bv && c < bc)) { bv = v; bc = c; }
        }
        int rg = by * TILE_M + tid;
        g_pval[(size_t)rg * NXT + bx] = bv;
        g_pcol[(size_t)rg * NXT + bx] = bc;
    }
}

// ---------------------------------------------------------------------------
// final reduce over 33 tile-partials + gather z_q / z_q_st
// ---------------------------------------------------------------------------
__global__ void argmax_final(float* __restrict__ idx_out,
                             float* __restrict__ zq,
                             float* __restrict__ zqst) {
    int r = blockIdx.x;
    __shared__ float sv;
    __shared__ int   si;
    if (threadIdx.x == 0) {
        float bv = -1e30f; int bc = 0x7fffffff;
        const float* pv = g_pval + (size_t)r * NXT;
        const int*   pc = g_pcol + (size_t)r * NXT;
        #pragma unroll
        for (int t = 0; t < NXT; t++) {
            float v = pv[t]; int c = pc[t];
            if (v > bv || (v == bv && c < bc)) { bv = v; bc = c; }
        }
        sv = bv; si = bc;
        idx_out[r]   = (float)bc;
        g_idx[r]     = bc;
        g_rowloss[r] = 1.0f - bv;
    }
    __syncthreads();
    int idx = si;
    const float4 cv = ((const float4*)(g_cb + (size_t)idx * DDIM))[threadIdx.x];
    const float4 xv = ((const float4*)(g_xn + (size_t)r   * DDIM))[threadIdx.x];
    ((float4*)(zq + (size_t)r * DDIM))[threadIdx.x] = cv;
    float4 st = make_float4(xv.x + (cv.x - xv.x), xv.y + (cv.y - xv.y),
                            xv.z + (cv.z - xv.z), xv.w + (cv.w - xv.w));
    ((float4*)(zqst + (size_t)r * DDIM))[threadIdx.x] = st;
}

__global__ void reduce_losses(float* __restrict__ scal) {
    __shared__ float scom[1024];
    __shared__ float svq[1024];
    __shared__ int   scnt[1024];
    float cm = 0.f, vq = 0.f; int cnt = 0;
    for (int r = threadIdx.x; r < NTOK; r += 1024) {
        float l = g_rowloss[r];
        cm += l;
        if (g_idx[r] >= NSEM) { vq += l; cnt++; }
    }
    scom[threadIdx.x] = cm; svq[threadIdx.x] = vq; scnt[threadIdx.x] = cnt;
    __syncthreads();
    #pragma unroll
    for (int off = 512; off; off >>= 1) {
        if (threadIdx.x < off) {
            scom[threadIdx.x] += scom[threadIdx.x + off];
            svq[threadIdx.x]  += svq[threadIdx.x + off];
            scnt[threadIdx.x] += scnt[threadIdx.x + off];
        }
        __syncthreads();
    }
    if (threadIdx.x == 0) {
        float commitment = scom[0] / (float)NTOK;
        float vql = svq[0] / ((float)scnt[0] + 1e-6f);
        scal[0] = vql;
        scal[1] = commitment;
        scal[2] = vql + 0.25f * commitment;
    }
}

// ---------------------------------------------------------------------------
extern "C" void kernel_launch(void* const* d_in, const int* in_sizes, int n_in,
                              void* d_out, int out_size) {
    const float* x   = (const float*)d_in[0];
    const float* sem = (const float*)d_in[1];
    const float* lrn = (const float*)d_in[2];
    float* out = (float*)d_out;

    float* logits = out;
    float* idxf   = out  + (size_t)NTOK * NCB;
    float* zq     = idxf + NTOK;
    float* zqst   = zq   + (size_t)NTOK * DDIM;
    float* scal   = zqst + (size_t)NTOK * DDIM;

    float *p_xn, *p_cb;
    __half *p_A, *p_B;
    cudaGetSymbolAddress((void**)&p_xn, g_xn);
    cudaGetSymbolAddress((void**)&p_cb, g_cb);
    cudaGetSymbolAddress((void**)&p_A,  g_Aext);
    cudaGetSymbolAddress((void**)&p_B,  g_Bext);

    norm_split<1><<<NTOK, 256>>>(x,   p_xn, p_A, 0);
    norm_split<0><<<NSEM, 256>>>(sem, p_cb, p_B, 0);
    norm_split<0><<<NLRN, 256>>>(lrn, p_cb + (size_t)NSEM * DDIM, p_B, NSEM);
    pad_bext<<<NCBP - NCB, 256>>>();

    int smem_bytes = STAGES * STAGE_BYTES;   // 192KB
    cudaFuncSetAttribute(gemm_mma, cudaFuncAttributeMaxDynamicSharedMemorySize, smem_bytes);
    dim3 grid(NCBP / TILE_N, NTOK / TILE_M);   // 33 x 64
    gemm_mma<<<grid, 256, smem_bytes>>>(p_A, p_B, logits);

    argmax_final<<<NTOK, 256>>>(idxf, zq, zqst);
    reduce_losses<<<1, 1024>>>(scal);
}

// round 5
// speedup vs baseline: 5.3729x; 1.7690x over previous
#include <cuda_runtime.h>
#include <cuda_fp16.h>
#include <math.h>
#include <stdint.h>

#define NTOK 8192
#define DDIM 1024
#define NSEM 8192
#define NLRN 128
#define NCB  8320           // NSEM + NLRN
#define NCBP 8448           // NCB padded to 33*256
#define NXT  33             // column tiles
#define NCAND (NXT * 2)     // 66 top-2-per-tile candidates per row

#define TILE_M 128
#define TILE_N 256
#define BK     64           // fp16 elems per K-chunk (128B row)
#define NKCH   (DDIM / BK)  // 16
#define STAGES 4
#define A_BYTES (TILE_M * 128)            // 16KB
#define B_BYTES (TILE_N * 128)            // 32KB
#define STAGE_BYTES (A_BYTES + B_BYTES)   // 48KB

// ---------------- scratch (__device__ globals; no allocs) -------------------
__device__ __align__(128) float  g_xn[(size_t)NTOK * DDIM];
__device__ __align__(128) float  g_cb[(size_t)NCB * DDIM];
__device__ __align__(128) __half g_Ah[(size_t)NTOK * DDIM];
__device__ __align__(128) __half g_Bh[(size_t)NCBP * DDIM];
__device__ float g_p2val[(size_t)NTOK * NCAND];
__device__ int   g_p2col[(size_t)NTOK * NCAND];
__device__ float g_rowloss[NTOK];
__device__ int   g_idx[NTOK];

// ---------------- PTX helpers ----------------------------------------------
__device__ __forceinline__ uint32_t smem_u32(const void* p) {
    uint32_t a;
    asm("{ .reg .u64 t; cvta.to.shared.u64 t, %1; cvt.u32.u64 %0, t; }" : "=r"(a) : "l"(p));
    return a;
}
__device__ __forceinline__ uint32_t sw128(uint32_t x) { return x ^ ((x >> 3) & 0x70); }

__device__ __forceinline__ void cp_async16(uint32_t dst, const void* src) {
    asm volatile("cp.async.cg.shared.global [%0], [%1], 16;" :: "r"(dst), "l"(src) : "memory");
}
#define CP_COMMIT() asm volatile("cp.async.commit_group;" ::: "memory")
#define CP_WAIT(n)  asm volatile("cp.async.wait_group %0;" :: "n"(n) : "memory")

#define LDSM_X4(r0, r1, r2, r3, a) \
    asm volatile("ldmatrix.sync.aligned.m8n8.x4.shared.b16 {%0,%1,%2,%3}, [%4];" \
                 : "=r"(r0), "=r"(r1), "=r"(r2), "=r"(r3) : "r"(a))

#define MMA16816(c, a, b0, b1) \
    asm volatile("mma.sync.aligned.m16n8k16.row.col.f32.f16.f16.f32 " \
                 "{%0,%1,%2,%3},{%4,%5,%6,%7},{%8,%9},{%0,%1,%2,%3};" \
                 : "+f"((c)[0]), "+f"((c)[1]), "+f"((c)[2]), "+f"((c)[3]) \
                 : "r"((a)[0]), "r"((a)[1]), "r"((a)[2]), "r"((a)[3]), "r"(b0), "r"(b1))

// top-2 insert keeping (value desc, col asc) order
#define TOP2_INS(v, c, v1, c1, v2, c2) do {                                  \
    float _v = (v); int _c = (c);                                            \
    if (_v > (v1) || (_v == (v1) && _c < (c1))) {                            \
        (v2) = (v1); (c2) = (c1); (v1) = _v; (c1) = _c;                      \
    } else if (_v > (v2) || (_v == (v2) && _c < (c2))) {                     \
        (v2) = _v; (c2) = _c;                                                \
    }                                                                        \
} while (0)

// ---------------------------------------------------------------------------
// row L2-normalize -> f32 copy + fp16 copy
// ---------------------------------------------------------------------------
__global__ void norm_cast(const float* __restrict__ src, float* __restrict__ f32dst,
                          __half* __restrict__ hdst) {
    int r = blockIdx.x;
    int t = threadIdx.x;
    float4 v = ((const float4*)(src + (size_t)r * DDIM))[t];
    float ss = v.x * v.x + v.y * v.y + v.z * v.z + v.w * v.w;
    #pragma unroll
    for (int o = 16; o; o >>= 1) ss += __shfl_xor_sync(0xffffffffu, ss, o);
    __shared__ float red[8];
    __shared__ float inv_s;
    if ((t & 31) == 0) red[t >> 5] = ss;
    __syncthreads();
    if (t == 0) {
        float s = 0.f;
        #pragma unroll
        for (int i = 0; i < 8; i++) s += red[i];
        inv_s = 1.0f / fmaxf(sqrtf(s), 1e-8f);
    }
    __syncthreads();
    float inv = inv_s;
    float f[4] = { v.x * inv, v.y * inv, v.z * inv, v.w * inv };
    ((float4*)(f32dst + (size_t)r * DDIM))[t] = *(float4*)f;
    union { __half h[4]; uint2 u; } p;
    #pragma unroll
    for (int j = 0; j < 4; j++) p.h[j] = __float2half_rn(f[j]);
    *(uint2*)(hdst + (size_t)r * DDIM + 4 * t) = p.u;
}

__global__ void pad_bh() {   // zero rows [NCB, NCBP)
    int r = NCB + blockIdx.x;
    uint4 z = make_uint4(0, 0, 0, 0);
    uint4* p = (uint4*)(g_Bh + (size_t)r * DDIM);
    for (int i = threadIdx.x; i < DDIM * 2 / 16; i += blockDim.x) p[i] = z;
}

// ---------------------------------------------------------------------------
// fp16 mma.sync GEMM (K=1024) + fused per-tile top-2 row argmax.
// CTA 128x256, 8 warps (2x4), warp tile 64x64, BK=64, 4-stage cp.async.
// ---------------------------------------------------------------------------
__device__ __forceinline__ void load_chunk(const __half* __restrict__ Ah,
                                           const __half* __restrict__ Bh,
                                           uint32_t data_base, int stage,
                                           int by, int bx, int kc, int tid) {
    uint32_t sb = data_base + stage * STAGE_BYTES;
    const char* Ab = (const char*)Ah + (size_t)by * TILE_M * (DDIM * 2) + (size_t)kc * 128;
    const char* Bb = (const char*)Bh + (size_t)bx * TILE_N * (DDIM * 2) + (size_t)kc * 128;
    #pragma unroll
    for (int i = 0; i < 4; i++) {
        int c = tid + i * 256;
        int row = c >> 3, cg = c & 7;
        cp_async16(sb + sw128(row * 128 + cg * 16),
                   Ab + (size_t)row * (DDIM * 2) + cg * 16);
    }
    #pragma unroll
    for (int i = 0; i < 8; i++) {
        int c = tid + i * 256;
        int row = c >> 3, cg = c & 7;
        cp_async16(sb + A_BYTES + sw128(row * 128 + cg * 16),
                   Bb + (size_t)row * (DDIM * 2) + cg * 16);
    }
    CP_COMMIT();
}

__global__ void __launch_bounds__(256, 1)
gemm_mma(const __half* __restrict__ Ah, const __half* __restrict__ Bh,
         float* __restrict__ Cout) {
    extern __shared__ char smem[];
    uint32_t data_base = smem_u32(smem);

    int tid = threadIdx.x, wid = tid >> 5, lane = tid & 31;
    int bx = blockIdx.x, by = blockIdx.y;
    int warp_m = wid & 1;
    int warp_n = wid >> 1;

    int rowA = lane & 15;
    int kselA = (lane >> 4) * 16;
    int rowB = (lane & 7) + ((lane >> 4) & 1) * 8;
    int kselB = ((lane >> 3) & 1) * 16;

    float acc[4][8][4];
    #pragma unroll
    for (int i = 0; i < 4; i++)
        #pragma unroll
        for (int j = 0; j < 8; j++)
            #pragma unroll
            for (int q = 0; q < 4; q++) acc[i][j][q] = 0.f;

    load_chunk(Ah, Bh, data_base, 0, by, bx, 0, tid);
    load_chunk(Ah, Bh, data_base, 1, by, bx, 1, tid);
    load_chunk(Ah, Bh, data_base, 2, by, bx, 2, tid);

    for (int k = 0; k < NKCH; k++) {
        if (k < NKCH - 2)       CP_WAIT(2);
        else if (k == NKCH - 2) CP_WAIT(1);
        else                    CP_WAIT(0);
        __syncthreads();
        if (k + 3 < NKCH) {
            int ss = (k + 3) & (STAGES - 1);
            load_chunk(Ah, Bh, data_base, ss, by, bx, k + 3, tid);
        }
        int s = k & (STAGES - 1);
        uint32_t Ab = data_base + s * STAGE_BYTES;
        uint32_t Bb = Ab + A_BYTES;
        #pragma unroll
        for (int ks = 0; ks < 4; ks++) {
            uint32_t afr[4][4];
            #pragma unroll
            for (int mt = 0; mt < 4; mt++) {
                uint32_t off = (uint32_t)(warp_m * 64 + mt * 16 + rowA) * 128
                             + ks * 32 + kselA;
                LDSM_X4(afr[mt][0], afr[mt][1], afr[mt][2], afr[mt][3], Ab + sw128(off));
            }
            uint32_t bfr[4][4];
            #pragma unroll
            for (int np = 0; np < 4; np++) {
                uint32_t off = (uint32_t)(warp_n * 64 + np * 16 + rowB) * 128
                             + ks * 32 + kselB;
                LDSM_X4(bfr[np][0], bfr[np][1], bfr[np][2], bfr[np][3], Bb + sw128(off));
            }
            #pragma unroll
            for (int mt = 0; mt < 4; mt++)
                #pragma unroll
                for (int nt = 0; nt < 8; nt++)
                    MMA16816(acc[mt][nt], afr[mt],
                             bfr[nt >> 1][(nt & 1) * 2], bfr[nt >> 1][(nt & 1) * 2 + 1]);
        }
    }
    __syncthreads();   // compute done; reuse smem for reductions

    // ---- store logits ----
    int row_base = by * TILE_M + warp_m * 64;
    int col_base = bx * TILE_N + warp_n * 64;
    #pragma unroll
    for (int mt = 0; mt < 4; mt++) {
        int r0 = row_base + mt * 16 + (lane >> 2);
        #pragma unroll
        for (int nt = 0; nt < 8; nt++) {
            int c0 = col_base + nt * 8 + (lane & 3) * 2;
            if (c0 < NCB) {
                float2* p0 = (float2*)(Cout + (size_t)r0 * NCB + c0);
                float2* p1 = (float2*)(Cout + (size_t)(r0 + 8) * NCB + c0);
                *p0 = make_float2(acc[mt][nt][0], acc[mt][nt][1]);
                *p1 = make_float2(acc[mt][nt][2], acc[mt][nt][3]);
            }
        }
    }

    // ---- fused per-tile TOP-2 row argmax ----
    float* bufv = (float*)smem;            // [128][4][2]
    int*   bufi = (int*)(smem + 4096);     // [128][4][2]
    #pragma unroll
    for (int mt = 0; mt < 4; mt++) {
        #pragma unroll
        for (int h = 0; h < 2; h++) {
            float v1 = -1e30f, v2 = -1e30f;
            int   c1 = 0x7fffffff, c2 = 0x7fffffff;
            #pragma unroll
            for (int nt = 0; nt < 8; nt++) {
                #pragma unroll
                for (int qq = 0; qq < 2; qq++) {
                    int colg = col_base + nt * 8 + (lane & 3) * 2 + qq;
                    float v = (colg < NCB) ? acc[mt][nt][h * 2 + qq] : -1e30f;
                    TOP2_INS(v, colg, v1, c1, v2, c2);
                }
            }
            #pragma unroll
            for (int off = 1; off <= 2; off <<= 1) {
                float ov1 = __shfl_xor_sync(0xffffffffu, v1, off);
                int   oc1 = __shfl_xor_sync(0xffffffffu, c1, off);
                float ov2 = __shfl_xor_sync(0xffffffffu, v2, off);
                int   oc2 = __shfl_xor_sync(0xffffffffu, c2, off);
                TOP2_INS(ov1, oc1, v1, c1, v2, c2);
                TOP2_INS(ov2, oc2, v1, c1, v2, c2);
            }
            if ((lane & 3) == 0) {
                int rl = warp_m * 64 + mt * 16 + (lane >> 2) + h * 8;
                bufv[(rl * 4 + warp_n) * 2 + 0] = v1;
                bufv[(rl * 4 + warp_n) * 2 + 1] = v2;
                bufi[(rl * 4 + warp_n) * 2 + 0] = c1;
                bufi[(rl * 4 + warp_n) * 2 + 1] = c2;
            }
        }
    }
    __syncthreads();
    if (tid < 128) {
        float v1 = -1e30f, v2 = -1e30f;
        int   c1 = 0x7fffffff, c2 = 0x7fffffff;
        #pragma unroll
        for (int w = 0; w < 4; w++) {
            TOP2_INS(bufv[(tid * 4 + w) * 2 + 0], bufi[(tid * 4 + w) * 2 + 0], v1, c1, v2, c2);
            TOP2_INS(bufv[(tid * 4 + w) * 2 + 1], bufi[(tid * 4 + w) * 2 + 1], v1, c1, v2, c2);
        }
        size_t base = ((size_t)(by * TILE_M + tid) * NXT + bx) * 2;
        g_p2val[base + 0] = v1; g_p2val[base + 1] = v2;
        g_p2col[base + 0] = c1; g_p2col[base + 1] = c2;
    }
}

// ---------------------------------------------------------------------------
// exact rescoring of near-max candidates (fp64 dot) + gather z_q / z_q_st
// ---------------------------------------------------------------------------
__global__ void rescore_gather(float* __restrict__ idx_out,
                               float* __restrict__ zq,
                               float* __restrict__ zqst) {
    int r = blockIdx.x;
    int t = threadIdx.x;
    __shared__ float  cval[NCAND];
    __shared__ int    ccol[NCAND];
    __shared__ float  smax;
    __shared__ int    ncand;
    __shared__ int    clist[NCAND];
    __shared__ double dred[256];
    __shared__ double sbest;
    __shared__ int    sbestc;

    if (t < NCAND) {
        cval[t] = g_p2val[(size_t)r * NCAND + t];
        ccol[t] = g_p2col[(size_t)r * NCAND + t];
    }
    if (t == 0) ncand = 0;
    __syncthreads();
    if (t == 0) {
        float m = -1e30f;
        #pragma unroll
        for (int i = 0; i < NCAND; i++) m = fmaxf(m, cval[i]);
        smax = m;
    }
    __syncthreads();
    if (t < NCAND && cval[t] >= smax - 1.5e-4f && ccol[t] < NCB) {
        int s = atomicAdd(&ncand, 1);
        clist[s] = ccol[t];
    }
    __syncthreads();

    int n = ncand;
    double bestv = -1e30; int bestc = 0x7fffffff;
    const float4 xv = ((const float4*)(g_xn + (size_t)r * DDIM))[t];
    for (int i = 0; i < n; i++) {
        int c = clist[i];
        const float4 cv = ((const float4*)(g_cb + (size_t)c * DDIM))[t];
        double d = (double)xv.x * cv.x + (double)xv.y * cv.y
                 + (double)xv.z * cv.z + (double)xv.w * cv.w;
        dred[t] = d;
        __syncthreads();
        #pragma unroll
        for (int off = 128; off; off >>= 1) {
            if (t < off) dred[t] += dred[t + off];
            __syncthreads();
        }
        double tot = dred[0];
        __syncthreads();
        if (tot > bestv || (tot == bestv && c < bestc)) { bestv = tot; bestc = c; }
    }
    if (t == 0) { sbest = bestv; sbestc = bestc; }
    __syncthreads();
    bestc = sbestc; bestv = sbest;

    if (t == 0) {
        idx_out[r]   = (float)bestc;
        g_idx[r]     = bestc;
        g_rowloss[r] = 1.0f - (float)bestv;
    }
    const float4 cv = ((const float4*)(g_cb + (size_t)bestc * DDIM))[t];
    ((float4*)(zq + (size_t)r * DDIM))[t] = cv;
    float4 st = make_float4(xv.x + (cv.x - xv.x), xv.y + (cv.y - xv.y),
                            xv.z + (cv.z - xv.z), xv.w + (cv.w - xv.w));
    ((float4*)(zqst + (size_t)r * DDIM))[t] = st;
}

__global__ void reduce_losses(float* __restrict__ scal) {
    __shared__ float scom[1024];
    __shared__ float svq[1024];
    __shared__ int   scnt[1024];
    float cm = 0.f, vq = 0.f; int cnt = 0;
    for (int r = threadIdx.x; r < NTOK; r += 1024) {
        float l = g_rowloss[r];
        cm += l;
        if (g_idx[r] >= NSEM) { vq += l; cnt++; }
    }
    scom[threadIdx.x] = cm; svq[threadIdx.x] = vq; scnt[threadIdx.x] = cnt;
    __syncthreads();
    #pragma unroll
    for (int off = 512; off; off >>= 1) {
        if (threadIdx.x < off) {
            scom[threadIdx.x] += scom[threadIdx.x + off];
            svq[threadIdx.x]  += svq[threadIdx.x + off];
            scnt[threadIdx.x] += scnt[threadIdx.x + off];
        }
        __syncthreads();
    }
    if (threadIdx.x == 0) {
        float commitment = scom[0] / (float)NTOK;
        float vql = svq[0] / ((float)scnt[0] + 1e-6f);
        scal[0] = vql;
        scal[1] = commitment;
        scal[2] = vql + 0.25f * commitment;
    }
}

// ---------------------------------------------------------------------------
extern "C" void kernel_launch(void* const* d_in, const int* in_sizes, int n_in,
                              void* d_out, int out_size) {
    const float* x   = (const float*)d_in[0];
    const float* sem = (const float*)d_in[1];
    const float* lrn = (const float*)d_in[2];
    float* out = (float*)d_out;

    float* logits = out;
    float* idxf   = out  + (size_t)NTOK * NCB;
    float* zq     = idxf + NTOK;
    float* zqst   = zq   + (size_t)NTOK * DDIM;
    float* scal   = zqst + (size_t)NTOK * DDIM;

    float *p_xn, *p_cb;
    __half *p_A, *p_B;
    cudaGetSymbolAddress((void**)&p_xn, g_xn);
    cudaGetSymbolAddress((void**)&p_cb, g_cb);
    cudaGetSymbolAddress((void**)&p_A,  g_Ah);
    cudaGetSymbolAddress((void**)&p_B,  g_Bh);

    norm_cast<<<NTOK, 256>>>(x,   p_xn, p_A);
    norm_cast<<<NSEM, 256>>>(sem, p_cb, p_B);
    norm_cast<<<NLRN, 256>>>(lrn, p_cb + (size_t)NSEM * DDIM, p_B + (size_t)NSEM * DDIM);
    pad_bh<<<NCBP - NCB, 256>>>();

    int smem_bytes = STAGES * STAGE_BYTES;   // 192KB
    cudaFuncSetAttribute(gemm_mma, cudaFuncAttributeMaxDynamicSharedMemorySize, smem_bytes);
    dim3 grid(NCBP / TILE_N, NTOK / TILE_M);   // 33 x 64
    gemm_mma<<<grid, 256, smem_bytes>>>(p_A, p_B, logits);

    rescore_gather<<<NTOK, 256>>>(idxf, zq, zqst);
    reduce_losses<<<1, 1024>>>(scal);
}

// round 6
// speedup vs baseline: 6.0460x; 1.1253x over previous
#include <cuda_runtime.h>
#include <cuda_fp16.h>
#include <math.h>
#include <stdint.h>

#define NTOK 8192
#define DDIM 1024
#define NSEM 8192
#define NLRN 128
#define NCB  8320           // NSEM + NLRN
#define NCBP 8448           // NCB padded to 66*128
#define NXT  66             // column tiles
#define NCAND (NXT * 2)     // 132 top-2-per-tile candidates per row

#define TILE_M 128
#define TILE_N 128
#define BK     64           // fp16 elems per K-chunk (128B row)
#define NKCH   (DDIM / BK)  // 16
#define STAGES 3
#define A_BYTES (TILE_M * 128)            // 16KB
#define B_BYTES (TILE_N * 128)            // 16KB
#define STAGE_BYTES (A_BYTES + B_BYTES)   // 32KB

// ---------------- scratch (__device__ globals; no allocs) -------------------
__device__ __align__(128) float  g_xn[(size_t)NTOK * DDIM];
__device__ __align__(128) float  g_cb[(size_t)NCB * DDIM];
__device__ __align__(128) __half g_Ah[(size_t)NTOK * DDIM];
__device__ __align__(128) __half g_Bh[(size_t)NCBP * DDIM];
__device__ float g_p2val[(size_t)NTOK * NCAND];
__device__ int   g_p2col[(size_t)NTOK * NCAND];
__device__ float g_rowloss[NTOK];
__device__ int   g_idx[NTOK];

// ---------------- PTX helpers ----------------------------------------------
__device__ __forceinline__ uint32_t smem_u32(const void* p) {
    uint32_t a;
    asm("{ .reg .u64 t; cvta.to.shared.u64 t, %1; cvt.u32.u64 %0, t; }" : "=r"(a) : "l"(p));
    return a;
}
__device__ __forceinline__ uint32_t sw128(uint32_t x) { return x ^ ((x >> 3) & 0x70); }

__device__ __forceinline__ void cp_async16(uint32_t dst, const void* src) {
    asm volatile("cp.async.cg.shared.global [%0], [%1], 16;" :: "r"(dst), "l"(src) : "memory");
}
#define CP_COMMIT() asm volatile("cp.async.commit_group;" ::: "memory")
#define CP_WAIT(n)  asm volatile("cp.async.wait_group %0;" :: "n"(n) : "memory")

#define LDSM_X4(r0, r1, r2, r3, a) \
    asm volatile("ldmatrix.sync.aligned.m8n8.x4.shared.b16 {%0,%1,%2,%3}, [%4];" \
                 : "=r"(r0), "=r"(r1), "=r"(r2), "=r"(r3) : "r"(a))

#define MMA16816(c, a, b0, b1) \
    asm volatile("mma.sync.aligned.m16n8k16.row.col.f32.f16.f16.f32 " \
                 "{%0,%1,%2,%3},{%4,%5,%6,%7},{%8,%9},{%0,%1,%2,%3};" \
                 : "+f"((c)[0]), "+f"((c)[1]), "+f"((c)[2]), "+f"((c)[3]) \
                 : "r"((a)[0]), "r"((a)[1]), "r"((a)[2]), "r"((a)[3]), "r"(b0), "r"(b1))

// top-2 insert keeping (value desc, col asc) order
#define TOP2_INS(v, c, v1, c1, v2, c2) do {                                  \
    float _v = (v); int _c = (c);                                            \
    if (_v > (v1) || (_v == (v1) && _c < (c1))) {                            \
        (v2) = (v1); (c2) = (c1); (v1) = _v; (c1) = _c;                      \
    } else if (_v > (v2) || (_v == (v2) && _c < (c2))) {                     \
        (v2) = _v; (c2) = _c;                                                \
    }                                                                        \
} while (0)

// ---------------------------------------------------------------------------
// row L2-normalize -> f32 copy + fp16 copy
// ---------------------------------------------------------------------------
__global__ void norm_cast(const float* __restrict__ src, float* __restrict__ f32dst,
                          __half* __restrict__ hdst) {
    int r = blockIdx.x;
    int t = threadIdx.x;
    float4 v = ((const float4*)(src + (size_t)r * DDIM))[t];
    float ss = v.x * v.x + v.y * v.y + v.z * v.z + v.w * v.w;
    #pragma unroll
    for (int o = 16; o; o >>= 1) ss += __shfl_xor_sync(0xffffffffu, ss, o);
    __shared__ float red[8];
    __shared__ float inv_s;
    if ((t & 31) == 0) red[t >> 5] = ss;
    __syncthreads();
    if (t == 0) {
        float s = 0.f;
        #pragma unroll
        for (int i = 0; i < 8; i++) s += red[i];
        inv_s = 1.0f / fmaxf(sqrtf(s), 1e-8f);
    }
    __syncthreads();
    float inv = inv_s;
    float f[4] = { v.x * inv, v.y * inv, v.z * inv, v.w * inv };
    ((float4*)(f32dst + (size_t)r * DDIM))[t] = *(float4*)f;
    union { __half h[4]; uint2 u; } p;
    #pragma unroll
    for (int j = 0; j < 4; j++) p.h[j] = __float2half_rn(f[j]);
    *(uint2*)(hdst + (size_t)r * DDIM + 4 * t) = p.u;
}

__global__ void pad_bh(int row0) {   // zero 64 rows starting at row0
    int r = row0 + blockIdx.x;
    uint4 z = make_uint4(0, 0, 0, 0);
    uint4* p = (uint4*)(g_Bh + (size_t)r * DDIM);
    for (int i = threadIdx.x; i < DDIM * 2 / 16; i += blockDim.x) p[i] = z;
}

// ---------------------------------------------------------------------------
// fp16 mma.sync GEMM (K=1024) + fused per-tile top-2 row argmax.
// CTA 128x128, 8 warps (2x4), warp tile 64x32, BK=64, 3-stage cp.async,
// 2 CTAs/SM (96KB smem, <=128 regs).
// ---------------------------------------------------------------------------
__device__ __forceinline__ void load_chunk(const __half* __restrict__ Ah,
                                           const __half* __restrict__ Bh,
                                           uint32_t data_base, int stage,
                                           int by, int bx, int kc, int tid) {
    uint32_t sb = data_base + stage * STAGE_BYTES;
    const char* Ab = (const char*)Ah + (size_t)by * TILE_M * (DDIM * 2) + (size_t)kc * 128;
    const char* Bb = (const char*)Bh + (size_t)bx * TILE_N * (DDIM * 2) + (size_t)kc * 128;
    #pragma unroll
    for (int i = 0; i < 4; i++) {
        int c = tid + i * 256;
        int row = c >> 3, cg = c & 7;
        cp_async16(sb + sw128(row * 128 + cg * 16),
                   Ab + (size_t)row * (DDIM * 2) + cg * 16);
    }
    #pragma unroll
    for (int i = 0; i < 4; i++) {
        int c = tid + i * 256;
        int row = c >> 3, cg = c & 7;
        cp_async16(sb + A_BYTES + sw128(row * 128 + cg * 16),
                   Bb + (size_t)row * (DDIM * 2) + cg * 16);
    }
    CP_COMMIT();
}

__global__ void __launch_bounds__(256, 2)
gemm_mma(const __half* __restrict__ Ah, const __half* __restrict__ Bh,
         float* __restrict__ Cout) {
    extern __shared__ char smem[];
    uint32_t data_base = smem_u32(smem);

    int tid = threadIdx.x, wid = tid >> 5, lane = tid & 31;
    int bx = blockIdx.x, by = blockIdx.y;
    int warp_m = wid & 1;       // 2 warps over M (64 rows each)
    int warp_n = wid >> 1;      // 4 warps over N (32 cols each)

    int rowA = lane & 15;
    int kselA = (lane >> 4) * 16;
    int rowB = (lane & 7) + ((lane >> 4) & 1) * 8;
    int kselB = ((lane >> 3) & 1) * 16;

    float acc[4][4][4];
    #pragma unroll
    for (int i = 0; i < 4; i++)
        #pragma unroll
        for (int j = 0; j < 4; j++)
            #pragma unroll
            for (int q = 0; q < 4; q++) acc[i][j][q] = 0.f;

    load_chunk(Ah, Bh, data_base, 0, by, bx, 0, tid);
    load_chunk(Ah, Bh, data_base, 1, by, bx, 1, tid);

    for (int k = 0; k < NKCH; k++) {
        if (k + 1 < NKCH) CP_WAIT(1); else CP_WAIT(0);
        __syncthreads();
        if (k + 2 < NKCH) {
            int ss = (k + 2) % STAGES;
            load_chunk(Ah, Bh, data_base, ss, by, bx, k + 2, tid);
        }
        int s = k % STAGES;
        uint32_t Ab = data_base + s * STAGE_BYTES;
        uint32_t Bb = Ab + A_BYTES;
        #pragma unroll
        for (int ks = 0; ks < 4; ks++) {
            uint32_t afr[4][4];
            #pragma unroll
            for (int mt = 0; mt < 4; mt++) {
                uint32_t off = (uint32_t)(warp_m * 64 + mt * 16 + rowA) * 128
                             + ks * 32 + kselA;
                LDSM_X4(afr[mt][0], afr[mt][1], afr[mt][2], afr[mt][3], Ab + sw128(off));
            }
            uint32_t bfr[2][4];
            #pragma unroll
            for (int np = 0; np < 2; np++) {
                uint32_t off = (uint32_t)(warp_n * 32 + np * 16 + rowB) * 128
                             + ks * 32 + kselB;
                LDSM_X4(bfr[np][0], bfr[np][1], bfr[np][2], bfr[np][3], Bb + sw128(off));
            }
            #pragma unroll
            for (int mt = 0; mt < 4; mt++)
                #pragma unroll
                for (int nt = 0; nt < 4; nt++)
                    MMA16816(acc[mt][nt], afr[mt],
                             bfr[nt >> 1][(nt & 1) * 2], bfr[nt >> 1][(nt & 1) * 2 + 1]);
        }
    }
    __syncthreads();   // compute done; reuse smem for reductions

    // ---- store logits ----
    int row_base = by * TILE_M + warp_m * 64;
    int col_base = bx * TILE_N + warp_n * 32;
    #pragma unroll
    for (int mt = 0; mt < 4; mt++) {
        int r0 = row_base + mt * 16 + (lane >> 2);
        #pragma unroll
        for (int nt = 0; nt < 4; nt++) {
            int c0 = col_base + nt * 8 + (lane & 3) * 2;
            if (c0 < NCB) {
                float2* p0 = (float2*)(Cout + (size_t)r0 * NCB + c0);
                float2* p1 = (float2*)(Cout + (size_t)(r0 + 8) * NCB + c0);
                *p0 = make_float2(acc[mt][nt][0], acc[mt][nt][1]);
                *p1 = make_float2(acc[mt][nt][2], acc[mt][nt][3]);
            }
        }
    }

    // ---- fused per-tile TOP-2 row argmax ----
    float* bufv = (float*)smem;            // [128][4][2]
    int*   bufi = (int*)(smem + 4096);     // [128][4][2]
    #pragma unroll
    for (int mt = 0; mt < 4; mt++) {
        #pragma unroll
        for (int h = 0; h < 2; h++) {
            float v1 = -1e30f, v2 = -1e30f;
            int   c1 = 0x7fffffff, c2 = 0x7fffffff;
            #pragma unroll
            for (int nt = 0; nt < 4; nt++) {
                #pragma unroll
                for (int qq = 0; qq < 2; qq++) {
                    int colg = col_base + nt * 8 + (lane & 3) * 2 + qq;
                    float v = (colg < NCB) ? acc[mt][nt][h * 2 + qq] : -1e30f;
                    TOP2_INS(v, colg, v1, c1, v2, c2);
                }
            }
            #pragma unroll
            for (int off = 1; off <= 2; off <<= 1) {
                float ov1 = __shfl_xor_sync(0xffffffffu, v1, off);
                int   oc1 = __shfl_xor_sync(0xffffffffu, c1, off);
                float ov2 = __shfl_xor_sync(0xffffffffu, v2, off);
                int   oc2 = __shfl_xor_sync(0xffffffffu, c2, off);
                TOP2_INS(ov1, oc1, v1, c1, v2, c2);
                TOP2_INS(ov2, oc2, v1, c1, v2, c2);
            }
            if ((lane & 3) == 0) {
                int rl = warp_m * 64 + mt * 16 + (lane >> 2) + h * 8;
                bufv[(rl * 4 + warp_n) * 2 + 0] = v1;
                bufv[(rl * 4 + warp_n) * 2 + 1] = v2;
                bufi[(rl * 4 + warp_n) * 2 + 0] = c1;
                bufi[(rl * 4 + warp_n) * 2 + 1] = c2;
            }
        }
    }
    __syncthreads();
    if (tid < 128) {
        float v1 = -1e30f, v2 = -1e30f;
        int   c1 = 0x7fffffff, c2 = 0x7fffffff;
        #pragma unroll
        for (int w = 0; w < 4; w++) {
            TOP2_INS(bufv[(tid * 4 + w) * 2 + 0], bufi[(tid * 4 + w) * 2 + 0], v1, c1, v2, c2);
            TOP2_INS(bufv[(tid * 4 + w) * 2 + 1], bufi[(tid * 4 + w) * 2 + 1], v1, c1, v2, c2);
        }
        size_t base = ((size_t)(by * TILE_M + tid) * NXT + bx) * 2;
        g_p2val[base + 0] = v1; g_p2val[base + 1] = v2;
        g_p2col[base + 0] = c1; g_p2col[base + 1] = c2;
    }
}

// ---------------------------------------------------------------------------
// exact rescoring of near-max candidates (fp64 dot) + gather z_q / z_q_st
// ---------------------------------------------------------------------------
__global__ void rescore_gather(float* __restrict__ idx_out,
                               float* __restrict__ zq,
                               float* __restrict__ zqst) {
    int r = blockIdx.x;
    int t = threadIdx.x;
    __shared__ float  cval[NCAND];
    __shared__ int    ccol[NCAND];
    __shared__ float  smax;
    __shared__ int    ncand;
    __shared__ int    clist[NCAND];
    __shared__ double dred[256];
    __shared__ double sbest;
    __shared__ int    sbestc;

    if (t < NCAND) {
        cval[t] = g_p2val[(size_t)r * NCAND + t];
        ccol[t] = g_p2col[(size_t)r * NCAND + t];
    }
    if (t == 0) ncand = 0;
    __syncthreads();
    if (t == 0) {
        float m = -1e30f;
        #pragma unroll
        for (int i = 0; i < NCAND; i++) m = fmaxf(m, cval[i]);
        smax = m;
    }
    __syncthreads();
    if (t < NCAND && cval[t] >= smax - 1.5e-4f && ccol[t] < NCB) {
        int s = atomicAdd(&ncand, 1);
        clist[s] = ccol[t];
    }
    __syncthreads();

    int n = ncand;
    double bestv = -1e30; int bestc = 0x7fffffff;
    const float4 xv = ((const float4*)(g_xn + (size_t)r * DDIM))[t];
    for (int i = 0; i < n; i++) {
        int c = clist[i];
        const float4 cv = ((const float4*)(g_cb + (size_t)c * DDIM))[t];
        double d = (double)xv.x * cv.x + (double)xv.y * cv.y
                 + (double)xv.z * cv.z + (double)xv.w * cv.w;
        dred[t] = d;
        __syncthreads();
        #pragma unroll
        for (int off = 128; off; off >>= 1) {
            if (t < off) dred[t] += dred[t + off];
            __syncthreads();
        }
        double tot = dred[0];
        __syncthreads();
        if (tot > bestv || (tot == bestv && c < bestc)) { bestv = tot; bestc = c; }
    }
    if (t == 0) { sbest = bestv; sbestc = bestc; }
    __syncthreads();
    bestc = sbestc; bestv = sbest;

    if (t == 0) {
        idx_out[r]   = (float)bestc;
        g_idx[r]     = bestc;
        g_rowloss[r] = 1.0f - (float)bestv;
    }
    const float4 cv = ((const float4*)(g_cb + (size_t)bestc * DDIM))[t];
    ((float4*)(zq + (size_t)r * DDIM))[t] = cv;
    float4 st = make_float4(xv.x + (cv.x - xv.x), xv.y + (cv.y - xv.y),
                            xv.z + (cv.z - xv.z), xv.w + (cv.w - xv.w));
    ((float4*)(zqst + (size_t)r * DDIM))[t] = st;
}

__global__ void reduce_losses(float* __restrict__ scal) {
    __shared__ float scom[1024];
    __shared__ float svq[1024];
    __shared__ int   scnt[1024];
    float cm = 0.f, vq = 0.f; int cnt = 0;
    for (int r = threadIdx.x; r < NTOK; r += 1024) {
        float l = g_rowloss[r];
        cm += l;
        if (g_idx[r] >= NSEM) { vq += l; cnt++; }
    }
    scom[threadIdx.x] = cm; svq[threadIdx.x] = vq; scnt[threadIdx.x] = cnt;
    __syncthreads();
    #pragma unroll
    for (int off = 512; off; off >>= 1) {
        if (threadIdx.x < off) {
            scom[threadIdx.x] += scom[threadIdx.x + off];
            svq[threadIdx.x]  += svq[threadIdx.x + off];
            scnt[threadIdx.x] += scnt[threadIdx.x + off];
        }
        __syncthreads();
    }
    if (threadIdx.x == 0) {
        float commitment = scom[0] / (float)NTOK;
        float vql = svq[0] / ((float)scnt[0] + 1e-6f);
        scal[0] = vql;
        scal[1] = commitment;
        scal[2] = vql + 0.25f * commitment;
    }
}

// ---------------------------------------------------------------------------
extern "C" void kernel_launch(void* const* d_in, const int* in_sizes, int n_in,
                              void* d_out, int out_size) {
    const float* x   = (const float*)d_in[0];
    const float* sem = (const float*)d_in[1];
    const float* lrn = (const float*)d_in[2];
    float* out = (float*)d_out;

    float* logits = out;
    float* idxf   = out  + (size_t)NTOK * NCB;
    float* zq     = idxf + NTOK;
    float* zqst   = zq   + (size_t)NTOK * DDIM;
    float* scal   = zqst + (size_t)NTOK * DDIM;

    float *p_xn, *p_cb;
    __half *p_A, *p_B;
    cudaGetSymbolAddress((void**)&p_xn, g_xn);
    cudaGetSymbolAddress((void**)&p_cb, g_cb);
    cudaGetSymbolAddress((void**)&p_A,  g_Ah);
    cudaGetSymbolAddress((void**)&p_B,  g_Bh);

    // launch order chosen so gemm_mma is launch index 5 (ncu -s 5 -c 1)
    norm_cast<<<NTOK, 256>>>(x,   p_xn, p_A);                                        // 0
    norm_cast<<<NSEM, 256>>>(sem, p_cb, p_B);                                        // 1
    norm_cast<<<NLRN, 256>>>(lrn, p_cb + (size_t)NSEM * DDIM,
                             p_B + (size_t)NSEM * DDIM);                             // 2
    pad_bh<<<64, 256>>>(NCB);                                                        // 3
    pad_bh<<<64, 256>>>(NCB + 64);                                                   // 4

    int smem_bytes = STAGES * STAGE_BYTES;   // 96KB
    cudaFuncSetAttribute(gemm_mma, cudaFuncAttributeMaxDynamicSharedMemorySize, smem_bytes);
    dim3 grid(NCBP / TILE_N, NTOK / TILE_M);   // 66 x 64
    gemm_mma<<<grid, 256, smem_bytes>>>(p_A, p_B, logits);                           // 5

    rescore_gather<<<NTOK, 256>>>(idxf, zq, zqst);
    reduce_losses<<<1, 1024>>>(scal);
}